// round 15
// baseline (speedup 1.0000x reference)
#include <cuda_runtime.h>
#include <cuda_fp16.h>
#include <mma.h>
#include <cstdint>

using namespace nvcuda;

// Problem constants
#define S_DIM 8192
#define X_DIM 512
#define Q_DIM 512
#define ZV_DIM 512
#define H_DIM 8

// ---------------- scratch (device globals: allocation-free) ----------------
__device__ float g_kv[1024 * 512];                   // rows 0-511 = k, 512-1023 = v
__device__ float g_b2[H_DIM * 512];                  // bias2[h][a] = k @ bq[h]
__device__ __half g_xh[(size_t)S_DIM * X_DIM];       // x  [S, X]
__device__ __half g_ench[(size_t)1024 * S_DIM];      // enc0 rows 0-511, enc1 rows 512-1023
__device__ __half g_wqh[(size_t)H_DIM * Q_DIM * X_DIM];
__device__ __half g_wch[(size_t)ZV_DIM * H_DIM * ZV_DIM];
__device__ __half g_kvh[1024 * 512];                 // fp16 k (0-511) / v (512-1023)
__device__ __half g_w2h[(size_t)H_DIM * 512 * 512];  // W2[h] = k @ Wq[h]   [a, xi]
__device__ __half g_mh[(size_t)512 * H_DIM * 512];   // Mcat  [c, h*512+a]
__device__ __half g_eh[(size_t)H_DIM * S_DIM * 512]; // e logits -> softmax

// ---------------- cp.async helpers ----------------
__device__ __forceinline__ void cp_async16(void* smem_ptr, const void* gptr) {
    unsigned int saddr = (unsigned int)__cvta_generic_to_shared(smem_ptr);
    asm volatile("cp.async.cg.shared.global [%0], [%1], 16;\n" ::"r"(saddr), "l"(gptr));
}
__device__ __forceinline__ void cp_commit() {
    asm volatile("cp.async.commit_group;\n" ::);
}
template <int N>
__device__ __forceinline__ void cp_wait() {
    asm volatile("cp.async.wait_group %0;\n" ::"n"(N));
}

// ------------- GEMM: fp16 wmma 16x16x16, 128x128x64 tile, 8 warps (4x2),
//               256 threads, 3-stage cp.async (2 chunks prefetched ahead).
//               Round-8 proven tiling; regs cap occupancy at 2 CTAs/SM, so the
//               3rd stage (110.6KB total) costs no occupancy. -------------------
constexpr int BM = 128, BN = 128, BK = 64;
constexpr int LDA_S = BK + 8;     // 72 halves : As[BM][LDA_S]
constexpr int LDBT_S = BK + 8;    // 72 halves : Bst[BN][LDBT_S] (B row-major [N][K])
constexpr int LDBN_S = BN + 8;    // 136 halves: Bs[BK][LDBN_S]  (B row-major [K][N])
constexpr int LDC_S = BN + 8;     // 136 floats: Cs[BM][LDC_S]
constexpr int STAGE_H = BM * LDA_S + BN * LDBT_S;      // 18432 halves = 36864 B / stage
constexpr int NSTAGE = 3;
constexpr int GEMM_SMEM_BYTES = NSTAGE * STAGE_H * 2;  // 110592 (>= epilogue 69632)

template <bool BTRANS, bool AHEADED, bool ATOMIC, bool OUTH>
__global__ __launch_bounds__(256)
void gemm_f16_kernel(const __half* __restrict__ A, const __half* __restrict__ B,
                     void* __restrict__ Cv, const float* __restrict__ bias,
                     float alpha, int M, int N, int K,
                     int lda, int ldb, int ldc,
                     long long strideA, long long strideB, long long strideC,
                     long long strideBias, long long headSlab) {
    extern __shared__ __half smemh[];

    const int z = blockIdx.z;
    int kBegin = 0, kCount = K;
    if constexpr (ATOMIC) {
        kCount = K / gridDim.z;
        kBegin = z * kCount;
    } else {
        A += z * strideA;
        B += z * strideB;
        if (bias) bias += z * strideBias;
    }
    const int mBase = blockIdx.y * BM;
    const int nBase = blockIdx.x * BN;

    const int tid = threadIdx.x;
    const int warp = tid >> 5;
    const int wm = warp >> 1;  // 0..3 (32-row strip)
    const int wn = warp & 1;   // 0..1 (64-col strip)

    wmma::fragment<wmma::accumulator, 16, 16, 16, float> acc[2][4];
#pragma unroll
    for (int i = 0; i < 2; ++i)
#pragma unroll
        for (int j = 0; j < 4; ++j) wmma::fill_fragment(acc[i][j], 0.0f);

    // ---- async stage loader (16B = 8 halves per cp.async) ----
    auto load_stage = [&](int kc) {
        __half* As = smemh + (kc % NSTAGE) * STAGE_H;
        __half* Bs = As + BM * LDA_S;
        const int kcol = kBegin + kc * BK;
#pragma unroll
        for (int it = 0; it < 4; ++it) {
            const int idx = tid + it * 256;
            const int r = idx >> 3;   // 0..127
            const int c8 = idx & 7;
            const __half* src;
            if constexpr (AHEADED) {
                src = A + (long long)(kcol >> 9) * headSlab +
                      (long long)(mBase + r) * 512 + (kcol & 511) + c8 * 8;
            } else {
                src = A + (long long)(mBase + r) * lda + kcol + c8 * 8;
            }
            cp_async16(&As[r * LDA_S + c8 * 8], src);
        }
        if constexpr (BTRANS) {
#pragma unroll
            for (int it = 0; it < 4; ++it) {
                const int idx = tid + it * 256;
                const int n = idx >> 3;
                const int c8 = idx & 7;
                cp_async16(&Bs[n * LDBT_S + c8 * 8],
                           B + (long long)(nBase + n) * ldb + kcol + c8 * 8);
            }
        } else {
#pragma unroll
            for (int it = 0; it < 4; ++it) {
                const int idx = tid + it * 256;
                const int r = idx >> 4;   // 0..63
                const int c8 = idx & 15;  // 0..15
                cp_async16(&Bs[r * LDBN_S + c8 * 8],
                           B + (long long)(kcol + r) * ldb + nBase + c8 * 8);
            }
        }
        cp_commit();
    };

    const int nChunks = kCount / BK;

    load_stage(0);
    if (nChunks > 1) load_stage(1);

    for (int kc = 0; kc < nChunks; ++kc) {
        if (kc + 1 < nChunks) cp_wait<1>();
        else cp_wait<0>();
        __syncthreads();  // stage kc ready; also orders buffer (kc+2)%3 reuse
        if (kc + 2 < nChunks) load_stage(kc + 2);

        const __half* As = smemh + (kc % NSTAGE) * STAGE_H;
        const __half* Bs = As + BM * LDA_S;

#pragma unroll
        for (int kk = 0; kk < BK / 16; ++kk) {
            wmma::fragment<wmma::matrix_a, 16, 16, 16, __half, wmma::row_major> af[2];
#pragma unroll
            for (int i = 0; i < 2; ++i)
                wmma::load_matrix_sync(af[i],
                                       &As[(wm * 32 + i * 16) * LDA_S + kk * 16], LDA_S);
#pragma unroll
            for (int j = 0; j < 4; ++j) {
                if constexpr (BTRANS) {
                    wmma::fragment<wmma::matrix_b, 16, 16, 16, __half,
                                   wmma::col_major> bf;
                    wmma::load_matrix_sync(
                        bf, &Bs[(wn * 64 + j * 16) * LDBT_S + kk * 16], LDBT_S);
#pragma unroll
                    for (int i = 0; i < 2; ++i)
                        wmma::mma_sync(acc[i][j], af[i], bf, acc[i][j]);
                } else {
                    wmma::fragment<wmma::matrix_b, 16, 16, 16, __half,
                                   wmma::row_major> bf;
                    wmma::load_matrix_sync(
                        bf, &Bs[(kk * 16) * LDBN_S + wn * 64 + j * 16], LDBN_S);
#pragma unroll
                    for (int i = 0; i < 2; ++i)
                        wmma::mma_sync(acc[i][j], af[i], bf, acc[i][j]);
                }
            }
        }
    }
    __syncthreads();  // stage buffers free for epilogue reuse

    // ---- epilogue: accum -> smem (fp32) -> coalesced global stores ----
    float* Cs = reinterpret_cast<float*>(smemh);  // [BM][LDC_S]
#pragma unroll
    for (int i = 0; i < 2; ++i)
#pragma unroll
        for (int j = 0; j < 4; ++j)
            wmma::store_matrix_sync(&Cs[(wm * 32 + i * 16) * LDC_S + wn * 64 + j * 16],
                                    acc[i][j], LDC_S, wmma::mem_row_major);
    __syncthreads();

#pragma unroll
    for (int it = 0; it < 16; ++it) {
        const int idx = tid + it * 256;  // 0..4095
        const int r = idx >> 5;          // 0..127
        const int c4 = idx & 31;         // 0..31 (4-wide columns)
        float4 v = *reinterpret_cast<float4*>(&Cs[r * LDC_S + c4 * 4]);
        const int ncol = nBase + c4 * 4;
        if constexpr (ATOMIC) {
            float* dst = reinterpret_cast<float*>(Cv) + (long long)(mBase + r) * ldc + ncol;
            atomicAdd(dst + 0, v.x);
            atomicAdd(dst + 1, v.y);
            atomicAdd(dst + 2, v.z);
            atomicAdd(dst + 3, v.w);
        } else {
            if (bias != nullptr) {
                v.x += bias[ncol + 0];
                v.y += bias[ncol + 1];
                v.z += bias[ncol + 2];
                v.w += bias[ncol + 3];
            }
            v.x *= alpha; v.y *= alpha; v.z *= alpha; v.w *= alpha;
            if constexpr (OUTH) {
                __half* dst = reinterpret_cast<__half*>(Cv) + z * strideC +
                              (long long)(mBase + r) * ldc + ncol;
                *reinterpret_cast<__half2*>(dst) = __floats2half2_rn(v.x, v.y);
                *reinterpret_cast<__half2*>(dst + 2) = __floats2half2_rn(v.z, v.w);
            } else {
                float* dst = reinterpret_cast<float*>(Cv) + z * strideC +
                             (long long)(mBase + r) * ldc + ncol;
                *reinterpret_cast<float4*>(dst) = v;
            }
        }
    }
}

// ---- mega convert: all five inputs fp32->fp16 + zero the kv accumulator ----
// Regions (in float4 units, R = 2^19): [0,2R) x, [2R,4R) enc0, [4R,6R) enc1,
// [6R,7R) Wq, [7R,8R) Wc, [8R, 8R+2^17) zero kv.
__global__ void megacvt_kernel(const float* __restrict__ x,
                               const float* __restrict__ e0,
                               const float* __restrict__ e1,
                               const float* __restrict__ wq,
                               const float* __restrict__ wc,
                               __half* __restrict__ xh, __half* __restrict__ ench,
                               __half* __restrict__ wqh, __half* __restrict__ wch,
                               float* __restrict__ kv) {
    const long long R = 1LL << 19;
    long long i = (long long)blockIdx.x * blockDim.x + threadIdx.x;
    if (i >= 8 * R) {
        long long z = i - 8 * R;
        if (z < (1LL << 17))
            reinterpret_cast<float4*>(kv)[z] = make_float4(0.f, 0.f, 0.f, 0.f);
        return;
    }
    const float* s;
    __half* d;
    long long j;
    if (i < 2 * R)      { j = i;         s = x;  d = xh; }
    else if (i < 4 * R) { j = i - 2 * R; s = e0; d = ench; }
    else if (i < 6 * R) { j = i - 4 * R; s = e1; d = ench + (size_t)512 * S_DIM; }
    else if (i < 7 * R) { j = i - 6 * R; s = wq; d = wqh; }
    else                { j = i - 7 * R; s = wc; d = wch; }
    float4 v = reinterpret_cast<const float4*>(s)[j];
    __half2* o2 = reinterpret_cast<__half2*>(d) + 2 * j;
    o2[0] = __floats2half2_rn(v.x, v.y);
    o2[1] = __floats2half2_rn(v.z, v.w);
}

// ---------------- bias2[h][a] = sum_q bq[h][q] * k[a][q]  (fp32) ----------------
__global__ void bias2_kernel(const float* __restrict__ kmat,
                             const float* __restrict__ bq, float* __restrict__ b2) {
    const int gw = (blockIdx.x * blockDim.x + threadIdx.x) >> 5;  // global warp id
    const int lane = threadIdx.x & 31;
    if (gw >= H_DIM * 512) return;
    const int h = gw >> 9;
    const int a = gw & 511;
    const float* kr = kmat + a * 512;
    const float* bqr = bq + h * 512;
    float s = 0.0f;
#pragma unroll 4
    for (int q = lane; q < 512; q += 32) s += bqr[q] * kr[q];
#pragma unroll
    for (int o = 16; o; o >>= 1) s += __shfl_xor_sync(0xffffffffu, s, o);
    if (lane == 0) b2[gw] = s;
}

// ---------------- softmax over half rows of 512 (1 warp per row) ----------------
__global__ void softmax512_half_kernel(__half* __restrict__ data, int rows) {
    const int row = blockIdx.x * blockDim.y + threadIdx.y;
    if (row >= rows) return;
    __half* p = data + (long long)row * 512;
    const int lane = threadIdx.x;
    uint4* p16 = reinterpret_cast<uint4*>(p);
    uint4 u[2];
    float f[16];
#pragma unroll
    for (int i = 0; i < 2; ++i) u[i] = p16[lane + i * 32];
#pragma unroll
    for (int i = 0; i < 2; ++i) {
        const __half2* h2 = reinterpret_cast<const __half2*>(&u[i]);
#pragma unroll
        for (int j = 0; j < 4; ++j) {
            float2 fv = __half22float2(h2[j]);
            f[i * 8 + j * 2 + 0] = fv.x;
            f[i * 8 + j * 2 + 1] = fv.y;
        }
    }
    float mx = -3.0e38f;
#pragma unroll
    for (int i = 0; i < 16; ++i) mx = fmaxf(mx, f[i]);
#pragma unroll
    for (int o = 16; o; o >>= 1) mx = fmaxf(mx, __shfl_xor_sync(0xffffffffu, mx, o));
    float sum = 0.0f;
#pragma unroll
    for (int i = 0; i < 16; ++i) { f[i] = __expf(f[i] - mx); sum += f[i]; }
#pragma unroll
    for (int o = 16; o; o >>= 1) sum += __shfl_xor_sync(0xffffffffu, sum, o);
    const float inv = 1.0f / sum;
#pragma unroll
    for (int i = 0; i < 2; ++i) {
        __half2* h2 = reinterpret_cast<__half2*>(&u[i]);
#pragma unroll
        for (int j = 0; j < 4; ++j)
            h2[j] = __floats2half2_rn(f[i * 8 + j * 2] * inv, f[i * 8 + j * 2 + 1] * inv);
        p16[lane + i * 32] = u[i];
    }
}

__global__ void f2h_kernel(const float* __restrict__ in, __half* __restrict__ out,
                           int n4) {
    const int i = blockIdx.x * blockDim.x + threadIdx.x;
    if (i < n4) {
        float4 v = reinterpret_cast<const float4*>(in)[i];
        __half2* o2 = reinterpret_cast<__half2*>(out) + 2 * i;
        o2[0] = __floats2half2_rn(v.x, v.y);
        o2[1] = __floats2half2_rn(v.z, v.w);
    }
}

// ---------------- launcher ----------------
extern "C" void kernel_launch(void* const* d_in, const int* in_sizes, int n_in,
                              void* d_out, int out_size) {
    const float* x    = (const float*)d_in[0];  // [S, X]
    const float* enc0 = (const float*)d_in[1];  // [Q, S]
    const float* enc1 = (const float*)d_in[2];  // [ZV, S]
    const float* Wq   = (const float*)d_in[3];  // [H, Q, X]
    const float* bq   = (const float*)d_in[4];  // [H, Q]
    const float* Wc   = (const float*)d_in[5];  // [ZV, H*ZV]
    const float* bc   = (const float*)d_in[6];  // [ZV]
    float* out = (float*)d_out;                 // [S, ZV]

    float *kv, *b2;
    __half *xh, *ench, *wqh, *wch, *kvh, *w2h, *mh, *eh;
    cudaGetSymbolAddress((void**)&kv, g_kv);
    cudaGetSymbolAddress((void**)&b2, g_b2);
    cudaGetSymbolAddress((void**)&xh, g_xh);
    cudaGetSymbolAddress((void**)&ench, g_ench);
    cudaGetSymbolAddress((void**)&wqh, g_wqh);
    cudaGetSymbolAddress((void**)&wch, g_wch);
    cudaGetSymbolAddress((void**)&kvh, g_kvh);
    cudaGetSymbolAddress((void**)&w2h, g_w2h);
    cudaGetSymbolAddress((void**)&mh, g_mh);
    cudaGetSymbolAddress((void**)&eh, g_eh);

    __half* kh = kvh;                 // rows 0-511
    __half* vh = kvh + 512 * 512;     // rows 512-1023

    cudaFuncSetAttribute(gemm_f16_kernel<false, false, true, false>,
                         cudaFuncAttributeMaxDynamicSharedMemorySize, GEMM_SMEM_BYTES);
    cudaFuncSetAttribute(gemm_f16_kernel<false, false, false, true>,
                         cudaFuncAttributeMaxDynamicSharedMemorySize, GEMM_SMEM_BYTES);
    cudaFuncSetAttribute(gemm_f16_kernel<true, false, false, true>,
                         cudaFuncAttributeMaxDynamicSharedMemorySize, GEMM_SMEM_BYTES);
    cudaFuncSetAttribute(gemm_f16_kernel<true, true, false, false>,
                         cudaFuncAttributeMaxDynamicSharedMemorySize, GEMM_SMEM_BYTES);

    const long long headSlab = (long long)S_DIM * 512;
    const float invSqrtQ = 0.044194173824159216f;  // 1/sqrt(512)
    const int T = 256;

    // ---- one mega-kernel: convert x/enc0/enc1/Wq/Wc to fp16 + zero kv ----
    {
        const long long total = (8LL << 19) + (1LL << 17);
        megacvt_kernel<<<(unsigned)((total + T - 1) / T), T>>>(
            x, enc0, enc1, Wq, Wc, xh, ench, wqh, wch, kv);
    }

    // kv = [enc0; enc1] @ x : M=1024, N=512, K=8192, split-K=8, fp32 atomics
    {
        dim3 g(512 / BN, 1024 / BM, 8);  // (4, 8, 8) = 256 CTAs
        gemm_f16_kernel<false, false, true, false><<<g, 256, GEMM_SMEM_BYTES>>>(
            ench, xh, kv, nullptr, 1.0f, 1024, 512, 8192, 8192, 512, 512,
            0, 0, 0, 0, 0);
    }
    // convert kv -> fp16 (one launch)
    f2h_kernel<<<((1024 * 512 / 4) + T - 1) / T, T>>>(kv, kvh, 1024 * 512 / 4);

    // bias2[h] = k @ bq[h]  (fp32, 4096 warp-dots; k = kv rows 0-511)
    bias2_kernel<<<(H_DIM * 512 * 32) / T, T>>>(kv, bq, b2);

    // W2[h] = k @ Wq[h] : [512,512]x[512,512], B-normal (Wq[h] is [q, xi])
    {
        dim3 g(4, 4, H_DIM);
        gemm_f16_kernel<false, false, false, true><<<g, 256, GEMM_SMEM_BYTES>>>(
            kh, wqh, w2h, nullptr, 1.0f, 512, 512, 512, 512, 512, 512,
            0, 512LL * 512, 512LL * 512, 0, 0);
    }

    // Mcat[c, h*512+a] = (Wc_h @ v)[c, a] : A=Wc_h (lda=4096, strideA=512), B=v normal
    {
        dim3 g(4, 4, H_DIM);
        gemm_f16_kernel<false, false, false, true><<<g, 256, GEMM_SMEM_BYTES>>>(
            wch, vh, mh, nullptr, 1.0f, 512, 512, 512, H_DIM * 512, 512, H_DIM * 512,
            512, 0, 512, 0, 0);
    }

    // e[h] = (x @ W2[h]^T + bias2[h]) / sqrt(Q)  -> eh (fp16)
    {
        dim3 g(4, S_DIM / BM, H_DIM);  // (4, 64, 8)
        gemm_f16_kernel<true, false, false, true><<<g, 256, GEMM_SMEM_BYTES>>>(
            xh, w2h, eh, b2, invSqrtQ, S_DIM, 512, 512, 512, 512, 512,
            0, 512LL * 512, headSlab, 512, 0);
    }

    softmax512_half_kernel<<<(H_DIM * S_DIM) / 8, dim3(32, 8)>>>(eh, H_DIM * S_DIM);

    // out = E_cat @ Mcat^T + bc : AHEADED A over eh, K=4096, BTRANS B=Mcat (ldb=4096)
    {
        dim3 g(4, S_DIM / BM, 1);
        gemm_f16_kernel<true, true, false, false><<<g, 256, GEMM_SMEM_BYTES>>>(
            eh, mh, out, bc, 1.0f, S_DIM, 512, H_DIM * 512, 512, H_DIM * 512, 512,
            0, 0, 0, 0, headSlab);
    }
}

// round 17
// speedup vs baseline: 1.0283x; 1.0283x over previous
#include <cuda_runtime.h>
#include <cuda_fp16.h>
#include <mma.h>
#include <cstdint>

using namespace nvcuda;

// Problem constants
#define S_DIM 8192
#define X_DIM 512
#define Q_DIM 512
#define ZV_DIM 512
#define H_DIM 8

// ---------------- scratch (device globals: allocation-free) ----------------
__device__ float g_kv[1024 * 512];                   // rows 0-511 = k, 512-1023 = v
__device__ float g_b2[H_DIM * 512];                  // bias2[h][a] = k @ bq[h]
__device__ __half g_xh[(size_t)S_DIM * X_DIM];       // x  [S, X]
__device__ __half g_ench[(size_t)1024 * S_DIM];      // enc0 rows 0-511, enc1 rows 512-1023
__device__ __half g_wqh[(size_t)H_DIM * Q_DIM * X_DIM];
__device__ __half g_wch[(size_t)ZV_DIM * H_DIM * ZV_DIM];
__device__ __half g_kvh[1024 * 512];                 // fp16 k (0-511) / v (512-1023)
__device__ __half g_w2h[(size_t)H_DIM * 512 * 512];  // W2[h] = k @ Wq[h]   [a, xi]
__device__ __half g_mh[(size_t)512 * H_DIM * 512];   // Mcat  [c, h*512+a]
__device__ __half g_eh[(size_t)H_DIM * S_DIM * 512]; // e logits -> softmax

// ---------------- cp.async helpers ----------------
__device__ __forceinline__ void cp_async16(void* smem_ptr, const void* gptr) {
    unsigned int saddr = (unsigned int)__cvta_generic_to_shared(smem_ptr);
    asm volatile("cp.async.cg.shared.global [%0], [%1], 16;\n" ::"r"(saddr), "l"(gptr));
}
__device__ __forceinline__ void cp_commit() {
    asm volatile("cp.async.commit_group;\n" ::);
}
template <int N>
__device__ __forceinline__ void cp_wait() {
    asm volatile("cp.async.wait_group %0;\n" ::"n"(N));
}

// ------------- GEMM: fp16 wmma 16x16x16, 128x128x64 tile, 8 warps, 2-stage cp.async ---
// (round-14 proven config: 32x64 warp tiles, 256 threads, ~74KB smem, 2 CTAs/SM)
constexpr int BM = 128, BN = 128, BK = 64;
constexpr int LDA_S = BK + 8;     // 72 halves : As[BM][LDA_S]
constexpr int LDBT_S = BK + 8;    // 72 halves : Bst[BN][LDBT_S] (B row-major [N][K])
constexpr int LDBN_S = BN + 8;    // 136 halves: Bs[BK][LDBN_S]  (B row-major [K][N])
constexpr int LDC_S = BN + 8;     // 136 floats: Cs[BM][LDC_S]
constexpr int STAGE_H = BM * LDA_S + BN * LDBT_S;      // 18432 halves = 36864 B / stage
constexpr int GEMM_SMEM_BYTES = 2 * STAGE_H * 2;       // 73728 (>= epilogue 69632)

template <bool BTRANS, bool AHEADED, bool ATOMIC, bool OUTH>
__global__ __launch_bounds__(256)
void gemm_f16_kernel(const __half* __restrict__ A, const __half* __restrict__ B,
                     void* __restrict__ Cv, const float* __restrict__ bias,
                     float alpha, int M, int N, int K,
                     int lda, int ldb, int ldc,
                     long long strideA, long long strideB, long long strideC,
                     long long strideBias, long long headSlab) {
    extern __shared__ __half smemh[];

    const int z = blockIdx.z;
    int kBegin = 0, kCount = K;
    if constexpr (ATOMIC) {
        kCount = K / gridDim.z;
        kBegin = z * kCount;
    } else {
        A += z * strideA;
        B += z * strideB;
        if (bias) bias += z * strideBias;
    }
    const int mBase = blockIdx.y * BM;
    const int nBase = blockIdx.x * BN;

    const int tid = threadIdx.x;
    const int warp = tid >> 5;
    const int wm = warp >> 1;  // 0..3 (32-row strip)
    const int wn = warp & 1;   // 0..1 (64-col strip)

    wmma::fragment<wmma::accumulator, 16, 16, 16, float> acc[2][4];
#pragma unroll
    for (int i = 0; i < 2; ++i)
#pragma unroll
        for (int j = 0; j < 4; ++j) wmma::fill_fragment(acc[i][j], 0.0f);

    // ---- async stage loader (16B = 8 halves per cp.async) ----
    auto load_stage = [&](int kc, int stage) {
        __half* As = smemh + stage * STAGE_H;
        __half* Bs = As + BM * LDA_S;
        const int kcol = kBegin + kc * BK;
#pragma unroll
        for (int it = 0; it < 4; ++it) {
            const int idx = tid + it * 256;
            const int r = idx >> 3;   // 0..127
            const int c8 = idx & 7;
            const __half* src;
            if constexpr (AHEADED) {
                src = A + (long long)(kcol >> 9) * headSlab +
                      (long long)(mBase + r) * 512 + (kcol & 511) + c8 * 8;
            } else {
                src = A + (long long)(mBase + r) * lda + kcol + c8 * 8;
            }
            cp_async16(&As[r * LDA_S + c8 * 8], src);
        }
        if constexpr (BTRANS) {
#pragma unroll
            for (int it = 0; it < 4; ++it) {
                const int idx = tid + it * 256;
                const int n = idx >> 3;
                const int c8 = idx & 7;
                cp_async16(&Bs[n * LDBT_S + c8 * 8],
                           B + (long long)(nBase + n) * ldb + kcol + c8 * 8);
            }
        } else {
#pragma unroll
            for (int it = 0; it < 4; ++it) {
                const int idx = tid + it * 256;
                const int r = idx >> 4;   // 0..63
                const int c8 = idx & 15;  // 0..15
                cp_async16(&Bs[r * LDBN_S + c8 * 8],
                           B + (long long)(kcol + r) * ldb + nBase + c8 * 8);
            }
        }
    };

    const int nChunks = kCount / BK;

    load_stage(0, 0);
    cp_commit();

    for (int kc = 0; kc < nChunks; ++kc) {
        cp_wait<0>();
        __syncthreads();
        if (kc + 1 < nChunks) {
            load_stage(kc + 1, (kc + 1) & 1);
            cp_commit();
        }
        const __half* As = smemh + (kc & 1) * STAGE_H;
        const __half* Bs = As + BM * LDA_S;

#pragma unroll
        for (int kk = 0; kk < BK / 16; ++kk) {
            wmma::fragment<wmma::matrix_a, 16, 16, 16, __half, wmma::row_major> af[2];
#pragma unroll
            for (int i = 0; i < 2; ++i)
                wmma::load_matrix_sync(af[i],
                                       &As[(wm * 32 + i * 16) * LDA_S + kk * 16], LDA_S);
#pragma unroll
            for (int j = 0; j < 4; ++j) {
                if constexpr (BTRANS) {
                    wmma::fragment<wmma::matrix_b, 16, 16, 16, __half,
                                   wmma::col_major> bf;
                    wmma::load_matrix_sync(
                        bf, &Bs[(wn * 64 + j * 16) * LDBT_S + kk * 16], LDBT_S);
#pragma unroll
                    for (int i = 0; i < 2; ++i)
                        wmma::mma_sync(acc[i][j], af[i], bf, acc[i][j]);
                } else {
                    wmma::fragment<wmma::matrix_b, 16, 16, 16, __half,
                                   wmma::row_major> bf;
                    wmma::load_matrix_sync(
                        bf, &Bs[(kk * 16) * LDBN_S + wn * 64 + j * 16], LDBN_S);
#pragma unroll
                    for (int i = 0; i < 2; ++i)
                        wmma::mma_sync(acc[i][j], af[i], bf, acc[i][j]);
                }
            }
        }
    }
    __syncthreads();  // stage buffers free for epilogue reuse

    // ---- epilogue: accum -> smem (fp32) -> coalesced global stores ----
    float* Cs = reinterpret_cast<float*>(smemh);  // [BM][LDC_S]
#pragma unroll
    for (int i = 0; i < 2; ++i)
#pragma unroll
        for (int j = 0; j < 4; ++j)
            wmma::store_matrix_sync(&Cs[(wm * 32 + i * 16) * LDC_S + wn * 64 + j * 16],
                                    acc[i][j], LDC_S, wmma::mem_row_major);
    __syncthreads();

#pragma unroll
    for (int it = 0; it < 16; ++it) {
        const int idx = tid + it * 256;  // 0..4095
        const int r = idx >> 5;          // 0..127
        const int c4 = idx & 31;         // 0..31 (4-wide columns)
        float4 v = *reinterpret_cast<float4*>(&Cs[r * LDC_S + c4 * 4]);
        const int ncol = nBase + c4 * 4;
        if constexpr (ATOMIC) {
            float* dst = reinterpret_cast<float*>(Cv) + (long long)(mBase + r) * ldc + ncol;
            atomicAdd(dst + 0, v.x);
            atomicAdd(dst + 1, v.y);
            atomicAdd(dst + 2, v.z);
            atomicAdd(dst + 3, v.w);
        } else {
            if (bias != nullptr) {
                v.x += bias[ncol + 0];
                v.y += bias[ncol + 1];
                v.z += bias[ncol + 2];
                v.w += bias[ncol + 3];
            }
            v.x *= alpha; v.y *= alpha; v.z *= alpha; v.w *= alpha;
            if constexpr (OUTH) {
                __half* dst = reinterpret_cast<__half*>(Cv) + z * strideC +
                              (long long)(mBase + r) * ldc + ncol;
                *reinterpret_cast<__half2*>(dst) = __floats2half2_rn(v.x, v.y);
                *reinterpret_cast<__half2*>(dst + 2) = __floats2half2_rn(v.z, v.w);
            } else {
                float* dst = reinterpret_cast<float*>(Cv) + z * strideC +
                             (long long)(mBase + r) * ldc + ncol;
                *reinterpret_cast<float4*>(dst) = v;
            }
        }
    }
}

// ---- dual small GEMM: one launch covers W2[h]=k@Wq[h] (z<8) and
//      Mcat_h=Wc_h@v (z>=8). All are 512^3, B-normal, fp16 out, no bias. ----
__global__ __launch_bounds__(256)
void gemm_small_dual(const __half* __restrict__ kh, const __half* __restrict__ wqh,
                     __half* __restrict__ w2h, const __half* __restrict__ wch,
                     const __half* __restrict__ vh, __half* __restrict__ mh) {
    extern __shared__ __half smemh[];
    const int z = blockIdx.z;
    const __half* A;
    const __half* B;
    __half* C;
    int lda, ldb, ldc;
    if (z < 8) {
        A = kh;                           lda = 512;
        B = wqh + ((long long)z << 18);   ldb = 512;   // z * 512*512
        C = w2h + ((long long)z << 18);   ldc = 512;
    } else {
        const int h = z - 8;
        A = wch + h * 512;                lda = 4096;
        B = vh;                           ldb = 512;
        C = mh + h * 512;                 ldc = 4096;
    }
    const int mBase = blockIdx.y * BM;
    const int nBase = blockIdx.x * BN;
    const int tid = threadIdx.x;
    const int warp = tid >> 5;
    const int wm = warp >> 1;
    const int wn = warp & 1;

    wmma::fragment<wmma::accumulator, 16, 16, 16, float> acc[2][4];
#pragma unroll
    for (int i = 0; i < 2; ++i)
#pragma unroll
        for (int j = 0; j < 4; ++j) wmma::fill_fragment(acc[i][j], 0.0f);

    auto load_stage = [&](int kc, int stage) {
        __half* As = smemh + stage * STAGE_H;
        __half* Bs = As + BM * LDA_S;
        const int kcol = kc * BK;
#pragma unroll
        for (int it = 0; it < 4; ++it) {
            const int idx = tid + it * 256;
            const int r = idx >> 3;
            const int c8 = idx & 7;
            cp_async16(&As[r * LDA_S + c8 * 8],
                       A + (long long)(mBase + r) * lda + kcol + c8 * 8);
        }
#pragma unroll
        for (int it = 0; it < 4; ++it) {
            const int idx = tid + it * 256;
            const int r = idx >> 4;   // 0..63
            const int c8 = idx & 15;  // 0..15
            cp_async16(&Bs[r * LDBN_S + c8 * 8],
                       B + (long long)(kcol + r) * ldb + nBase + c8 * 8);
        }
    };

    const int nChunks = 512 / BK;  // 8
    load_stage(0, 0);
    cp_commit();
    for (int kc = 0; kc < nChunks; ++kc) {
        cp_wait<0>();
        __syncthreads();
        if (kc + 1 < nChunks) {
            load_stage(kc + 1, (kc + 1) & 1);
            cp_commit();
        }
        const __half* As = smemh + (kc & 1) * STAGE_H;
        const __half* Bs = As + BM * LDA_S;
#pragma unroll
        for (int kk = 0; kk < BK / 16; ++kk) {
            wmma::fragment<wmma::matrix_a, 16, 16, 16, __half, wmma::row_major> af[2];
#pragma unroll
            for (int i = 0; i < 2; ++i)
                wmma::load_matrix_sync(af[i],
                                       &As[(wm * 32 + i * 16) * LDA_S + kk * 16], LDA_S);
#pragma unroll
            for (int j = 0; j < 4; ++j) {
                wmma::fragment<wmma::matrix_b, 16, 16, 16, __half, wmma::row_major> bf;
                wmma::load_matrix_sync(bf, &Bs[(kk * 16) * LDBN_S + wn * 64 + j * 16],
                                       LDBN_S);
#pragma unroll
                for (int i = 0; i < 2; ++i)
                    wmma::mma_sync(acc[i][j], af[i], bf, acc[i][j]);
            }
        }
    }
    __syncthreads();

    float* Cs = reinterpret_cast<float*>(smemh);
#pragma unroll
    for (int i = 0; i < 2; ++i)
#pragma unroll
        for (int j = 0; j < 4; ++j)
            wmma::store_matrix_sync(&Cs[(wm * 32 + i * 16) * LDC_S + wn * 64 + j * 16],
                                    acc[i][j], LDC_S, wmma::mem_row_major);
    __syncthreads();

#pragma unroll
    for (int it = 0; it < 16; ++it) {
        const int idx = tid + it * 256;
        const int r = idx >> 5;
        const int c4 = idx & 31;
        float4 v = *reinterpret_cast<float4*>(&Cs[r * LDC_S + c4 * 4]);
        __half* dst = C + (long long)(mBase + r) * ldc + nBase + c4 * 4;
        *reinterpret_cast<__half2*>(dst) = __floats2half2_rn(v.x, v.y);
        *reinterpret_cast<__half2*>(dst + 2) = __floats2half2_rn(v.z, v.w);
    }
}

// ---- mega convert: all five inputs fp32->fp16 + zero the kv accumulator ----
__global__ void megacvt_kernel(const float* __restrict__ x,
                               const float* __restrict__ e0,
                               const float* __restrict__ e1,
                               const float* __restrict__ wq,
                               const float* __restrict__ wc,
                               __half* __restrict__ xh, __half* __restrict__ ench,
                               __half* __restrict__ wqh, __half* __restrict__ wch,
                               float* __restrict__ kv) {
    const long long R = 1LL << 19;
    long long i = (long long)blockIdx.x * blockDim.x + threadIdx.x;
    if (i >= 8 * R) {
        long long z = i - 8 * R;
        if (z < (1LL << 17))
            reinterpret_cast<float4*>(kv)[z] = make_float4(0.f, 0.f, 0.f, 0.f);
        return;
    }
    const float* s;
    __half* d;
    long long j;
    if (i < 2 * R)      { j = i;         s = x;  d = xh; }
    else if (i < 4 * R) { j = i - 2 * R; s = e0; d = ench; }
    else if (i < 6 * R) { j = i - 4 * R; s = e1; d = ench + (size_t)512 * S_DIM; }
    else if (i < 7 * R) { j = i - 6 * R; s = wq; d = wqh; }
    else                { j = i - 7 * R; s = wc; d = wch; }
    float4 v = reinterpret_cast<const float4*>(s)[j];
    __half2* o2 = reinterpret_cast<__half2*>(d) + 2 * j;
    o2[0] = __floats2half2_rn(v.x, v.y);
    o2[1] = __floats2half2_rn(v.z, v.w);
}

// ---- fused: kv fp32->fp16 convert (blocks 0-511) + bias2 warp-dots (blocks 512+) ----
__global__ void kvcvt_bias2_kernel(const float* __restrict__ kv,
                                   __half* __restrict__ kvh,
                                   const float* __restrict__ bq,
                                   float* __restrict__ b2) {
    if (blockIdx.x < 512) {
        const int i = blockIdx.x * 256 + threadIdx.x;  // 0..131071 float4s
        float4 v = reinterpret_cast<const float4*>(kv)[i];
        __half2* o2 = reinterpret_cast<__half2*>(kvh) + 2 * i;
        o2[0] = __floats2half2_rn(v.x, v.y);
        o2[1] = __floats2half2_rn(v.z, v.w);
    } else {
        const int gw = ((blockIdx.x - 512) * 256 + threadIdx.x) >> 5;  // 0..4095
        const int lane = threadIdx.x & 31;
        const int h = gw >> 9;
        const int a = gw & 511;
        const float* kr = kv + a * 512;  // k rows 0-511
        const float* bqr = bq + h * 512;
        float s = 0.0f;
#pragma unroll 4
        for (int q = lane; q < 512; q += 32) s += bqr[q] * kr[q];
#pragma unroll
        for (int o = 16; o; o >>= 1) s += __shfl_xor_sync(0xffffffffu, s, o);
        if (lane == 0) b2[gw] = s;
    }
}

// ---------------- softmax over half rows of 512 (1 warp per row) ----------------
__global__ void softmax512_half_kernel(__half* __restrict__ data, int rows) {
    const int row = blockIdx.x * blockDim.y + threadIdx.y;
    if (row >= rows) return;
    __half* p = data + (long long)row * 512;
    const int lane = threadIdx.x;
    uint4* p16 = reinterpret_cast<uint4*>(p);
    uint4 u[2];
    float f[16];
#pragma unroll
    for (int i = 0; i < 2; ++i) u[i] = p16[lane + i * 32];
#pragma unroll
    for (int i = 0; i < 2; ++i) {
        const __half2* h2 = reinterpret_cast<const __half2*>(&u[i]);
#pragma unroll
        for (int j = 0; j < 4; ++j) {
            float2 fv = __half22float2(h2[j]);
            f[i * 8 + j * 2 + 0] = fv.x;
            f[i * 8 + j * 2 + 1] = fv.y;
        }
    }
    float mx = -3.0e38f;
#pragma unroll
    for (int i = 0; i < 16; ++i) mx = fmaxf(mx, f[i]);
#pragma unroll
    for (int o = 16; o; o >>= 1) mx = fmaxf(mx, __shfl_xor_sync(0xffffffffu, mx, o));
    float sum = 0.0f;
#pragma unroll
    for (int i = 0; i < 16; ++i) { f[i] = __expf(f[i] - mx); sum += f[i]; }
#pragma unroll
    for (int o = 16; o; o >>= 1) sum += __shfl_xor_sync(0xffffffffu, sum, o);
    const float inv = 1.0f / sum;
#pragma unroll
    for (int i = 0; i < 2; ++i) {
        __half2* h2 = reinterpret_cast<__half2*>(&u[i]);
#pragma unroll
        for (int j = 0; j < 4; ++j)
            h2[j] = __floats2half2_rn(f[i * 8 + j * 2] * inv, f[i * 8 + j * 2 + 1] * inv);
        p16[lane + i * 32] = u[i];
    }
}

// ---------------- launcher ----------------
extern "C" void kernel_launch(void* const* d_in, const int* in_sizes, int n_in,
                              void* d_out, int out_size) {
    const float* x    = (const float*)d_in[0];  // [S, X]
    const float* enc0 = (const float*)d_in[1];  // [Q, S]
    const float* enc1 = (const float*)d_in[2];  // [ZV, S]
    const float* Wq   = (const float*)d_in[3];  // [H, Q, X]
    const float* bq   = (const float*)d_in[4];  // [H, Q]
    const float* Wc   = (const float*)d_in[5];  // [ZV, H*ZV]
    const float* bc   = (const float*)d_in[6];  // [ZV]
    float* out = (float*)d_out;                 // [S, ZV]

    float *kv, *b2;
    __half *xh, *ench, *wqh, *wch, *kvh, *w2h, *mh, *eh;
    cudaGetSymbolAddress((void**)&kv, g_kv);
    cudaGetSymbolAddress((void**)&b2, g_b2);
    cudaGetSymbolAddress((void**)&xh, g_xh);
    cudaGetSymbolAddress((void**)&ench, g_ench);
    cudaGetSymbolAddress((void**)&wqh, g_wqh);
    cudaGetSymbolAddress((void**)&wch, g_wch);
    cudaGetSymbolAddress((void**)&kvh, g_kvh);
    cudaGetSymbolAddress((void**)&w2h, g_w2h);
    cudaGetSymbolAddress((void**)&mh, g_mh);
    cudaGetSymbolAddress((void**)&eh, g_eh);

    __half* kh = kvh;                 // rows 0-511
    __half* vh = kvh + 512 * 512;     // rows 512-1023

    cudaFuncSetAttribute(gemm_f16_kernel<false, false, true, false>,
                         cudaFuncAttributeMaxDynamicSharedMemorySize, GEMM_SMEM_BYTES);
    cudaFuncSetAttribute(gemm_f16_kernel<true, false, false, true>,
                         cudaFuncAttributeMaxDynamicSharedMemorySize, GEMM_SMEM_BYTES);
    cudaFuncSetAttribute(gemm_f16_kernel<true, true, false, false>,
                         cudaFuncAttributeMaxDynamicSharedMemorySize, GEMM_SMEM_BYTES);
    cudaFuncSetAttribute(gemm_small_dual,
                         cudaFuncAttributeMaxDynamicSharedMemorySize, GEMM_SMEM_BYTES);

    const long long headSlab = (long long)S_DIM * 512;
    const float invSqrtQ = 0.044194173824159216f;  // 1/sqrt(512)
    const int T = 256;

    // ---- one mega-kernel: convert x/enc0/enc1/Wq/Wc to fp16 + zero kv ----
    {
        const long long total = (8LL << 19) + (1LL << 17);
        megacvt_kernel<<<(unsigned)((total + T - 1) / T), T>>>(
            x, enc0, enc1, Wq, Wc, xh, ench, wqh, wch, kv);
    }

    // kv = [enc0; enc1] @ x : M=1024, N=512, K=8192, split-K=8, fp32 atomics
    {
        dim3 g(512 / BN, 1024 / BM, 8);  // (4, 8, 8) = 256 CTAs
        gemm_f16_kernel<false, false, true, false><<<g, 256, GEMM_SMEM_BYTES>>>(
            ench, xh, kv, nullptr, 1.0f, 1024, 512, 8192, 8192, 512, 512,
            0, 0, 0, 0, 0);
    }

    // fused: kv -> fp16 (blocks 0-511) + bias2[h] = k @ bq[h] (blocks 512-1023)
    kvcvt_bias2_kernel<<<1024, T>>>(kv, kvh, bq, b2);

    // dual small GEMM: z<8 -> W2[z] = k @ Wq[z] ; z>=8 -> Mcat_h = Wc_h @ v
    {
        dim3 g(4, 4, 16);  // 256 CTAs
        gemm_small_dual<<<g, 256, GEMM_SMEM_BYTES>>>(kh, wqh, w2h, wch, vh, mh);
    }

    // e[h] = (x @ W2[h]^T + bias2[h]) / sqrt(Q)  -> eh (fp16)
    {
        dim3 g(4, S_DIM / BM, H_DIM);  // (4, 64, 8)
        gemm_f16_kernel<true, false, false, true><<<g, 256, GEMM_SMEM_BYTES>>>(
            xh, w2h, eh, b2, invSqrtQ, S_DIM, 512, 512, 512, 512, 512,
            0, 512LL * 512, headSlab, 512, 0);
    }

    softmax512_half_kernel<<<(H_DIM * S_DIM) / 8, dim3(32, 8)>>>(eh, H_DIM * S_DIM);

    // out = E_cat @ Mcat^T + bc : AHEADED A over eh, K=4096, BTRANS B=Mcat (ldb=4096)
    {
        dim3 g(4, S_DIM / BM, 1);
        gemm_f16_kernel<true, true, false, false><<<g, 256, GEMM_SMEM_BYTES>>>(
            eh, mh, out, bc, 1.0f, S_DIM, 512, H_DIM * 512, 512, H_DIM * 512, 512,
            0, 0, 0, 0, headSlab);
    }
}